// round 9
// baseline (speedup 1.0000x reference)
#include <cuda_runtime.h>
#include <cuda_bf16.h>
#include <math.h>
#include <stdint.h>

#define BSZ   16384
#define IDIM  512
#define HDIM  512
#define LN_EPS 1e-5f

// ---------------- scratch (device globals: allocation-free) ----------------
__device__ float g_gates[(size_t)BSZ * 2048];  // raw gates pre-bias [B, 4H]
__device__ float g_s[(size_t)BSZ * HDIM];      // o * tanh(LN(cell))

// ---------------------------------------------------------------------------
// mma.sync bf16 GEMM (base ISA, sm_80+; compiles on plain sm_103 target).
// C[M,N] = A[M,K] * B[N,K]^T, fp32 in/out, bf16x3 split:
//   D += Ahi*Bhi + Ahi*Blo + Alo*Bhi   (fp32 accum; dropped lo*lo ~ 2^-17)
// Block tile 128x128, BK=32, 512 threads = 16 warps in 4x4 grid,
// warp tile 32x32 = 2(m) x 4(n) m16n8k16 atoms.
// Double-buffered smem (padded, conflict-free frag loads) + register prefetch.
// ---------------------------------------------------------------------------
#define BM   128
#define BN   128
#define BK   32
#define LDT  40                      // bf16 row stride (32 + 8 pad)
#define TILE_BYTES (128 * LDT * 2)   // 10240 B per tile
#define BUF_BYTES  (4 * TILE_BYTES)  // Ahi,Alo,Bhi,Blo
#define SMEM_BYTES (2 * BUF_BYTES)   // 81920 B double-buffered

__device__ __forceinline__ void mma_bf16(float* d, const uint32_t* a, const uint32_t* b) {
    asm volatile(
        "mma.sync.aligned.m16n8k16.row.col.f32.bf16.bf16.f32 "
        "{%0,%1,%2,%3}, {%4,%5,%6,%7}, {%8,%9}, {%0,%1,%2,%3};\n"
        : "+f"(d[0]), "+f"(d[1]), "+f"(d[2]), "+f"(d[3])
        : "r"(a[0]), "r"(a[1]), "r"(a[2]), "r"(a[3]), "r"(b[0]), "r"(b[1]));
}

__device__ __forceinline__ uint32_t ld32s(const __nv_bfloat16* p) {
    return *(const uint32_t*)p;
}

// Split fp32 -> (hi bf16, lo bf16 = bf16(v - float(hi))).
__device__ __forceinline__ void bf16split(float v, uint16_t& hb, uint16_t& lb) {
    __nv_bfloat16 h = __float2bfloat16(v);
    hb = __bfloat16_as_ushort(h);
    lb = __bfloat16_as_ushort(__float2bfloat16(v - __bfloat162float(h)));
}
__device__ __forceinline__ uint32_t pack16(uint16_t a, uint16_t b) {
    return (uint32_t)a | ((uint32_t)b << 16);
}

template <int NCHUNK, int SPLIT>
__global__ __launch_bounds__(512) void mma_gemm(
    const float* __restrict__ A1, const float* __restrict__ A2,
    const float* __restrict__ B,  float* __restrict__ C,
    int ldb, int ldc)
{
    extern __shared__ char smem[];

    const int tid  = threadIdx.x;
    const int wid  = tid >> 5;
    const int lane = tid & 31;
    const int wm   = wid >> 2;        // 0..3  (m warp row)
    const int wn   = wid & 3;         // 0..3  (n warp col)
    const int gid  = lane >> 2;       // 0..7
    const int ctid = lane & 3;        // 0..3

    const size_t rowA0 = (size_t)blockIdx.y * BM;
    const size_t rowB0 = (size_t)blockIdx.x * BN;

    float acc[2][4][4];
    #pragma unroll
    for (int i = 0; i < 2; i++)
        #pragma unroll
        for (int j = 0; j < 4; j++)
            #pragma unroll
            for (int q = 0; q < 4; q++) acc[i][j][q] = 0.f;

    // Per-thread loader slots: 2 float4 for A, 2 for B, fixed across chunks.
    // idx = tid + j*512; row = idx>>3 (8 float4 per 32-float row); c4 = idx&7.
    int l_row[2], l_c4[2];
    #pragma unroll
    for (int j = 0; j < 2; j++) {
        int idx = tid + j * 512;
        l_row[j] = idx >> 3;
        l_c4[j]  = idx & 7;
    }

    auto load_regs = [&](int c, float4* aR, float4* bR) {
        const float* Asrc = (c < SPLIT) ? A1 : A2;
        const int ka = (c < SPLIT) ? c * BK : (c - SPLIT) * BK;
        const int kb = c * BK;
        #pragma unroll
        for (int j = 0; j < 2; j++) {
            aR[j] = *(const float4*)&Asrc[(rowA0 + l_row[j]) * 512 + ka + l_c4[j] * 4];
            bR[j] = *(const float4*)&B[(rowB0 + l_row[j]) * (size_t)ldb + kb + l_c4[j] * 4];
        }
    };

    auto store_smem = [&](int buf, const float4* aR, const float4* bR) {
        char* base = smem + buf * BUF_BYTES;
        __nv_bfloat16* Ahi = (__nv_bfloat16*)(base);
        __nv_bfloat16* Alo = (__nv_bfloat16*)(base + TILE_BYTES);
        __nv_bfloat16* Bhi = (__nv_bfloat16*)(base + 2 * TILE_BYTES);
        __nv_bfloat16* Blo = (__nv_bfloat16*)(base + 3 * TILE_BYTES);
        #pragma unroll
        for (int j = 0; j < 2; j++) {
            int off = l_row[j] * LDT + l_c4[j] * 4;
            {
                float4 v = aR[j];
                uint16_t hx, lx, hy, ly, hz, lz, hw, lw;
                bf16split(v.x, hx, lx); bf16split(v.y, hy, ly);
                bf16split(v.z, hz, lz); bf16split(v.w, hw, lw);
                *(uint32_t*)&Ahi[off]     = pack16(hx, hy);
                *(uint32_t*)&Ahi[off + 2] = pack16(hz, hw);
                *(uint32_t*)&Alo[off]     = pack16(lx, ly);
                *(uint32_t*)&Alo[off + 2] = pack16(lz, lw);
            }
            {
                float4 v = bR[j];
                uint16_t hx, lx, hy, ly, hz, lz, hw, lw;
                bf16split(v.x, hx, lx); bf16split(v.y, hy, ly);
                bf16split(v.z, hz, lz); bf16split(v.w, hw, lw);
                *(uint32_t*)&Bhi[off]     = pack16(hx, hy);
                *(uint32_t*)&Bhi[off + 2] = pack16(hz, hw);
                *(uint32_t*)&Blo[off]     = pack16(lx, ly);
                *(uint32_t*)&Blo[off + 2] = pack16(lz, lw);
            }
        }
    };

    // ---- preload chunk 0 into buffer 0
    {
        float4 aR[2], bR[2];
        load_regs(0, aR, bR);
        store_smem(0, aR, bR);
    }
    __syncthreads();

    for (int c = 0; c < NCHUNK; c++) {
        const int cur = c & 1;
        const bool has_next = (c + 1 < NCHUNK);

        // ---- prefetch next chunk into registers
        float4 aR[2], bR[2];
        if (has_next) load_regs(c + 1, aR, bR);

        // ---- compute current buffer
        {
            char* base = smem + cur * BUF_BYTES;
            const __nv_bfloat16* Ahi = (const __nv_bfloat16*)(base);
            const __nv_bfloat16* Alo = (const __nv_bfloat16*)(base + TILE_BYTES);
            const __nv_bfloat16* Bhi = (const __nv_bfloat16*)(base + 2 * TILE_BYTES);
            const __nv_bfloat16* Blo = (const __nv_bfloat16*)(base + 3 * TILE_BYTES);

            #pragma unroll
            for (int ks = 0; ks < 2; ks++) {
                const int kb = ks * 16;
                uint32_t ah[2][4], al[2][4], bh[4][2], bl[4][2];
                #pragma unroll
                for (int ma = 0; ma < 2; ma++) {
                    int r0 = wm * 32 + ma * 16 + gid;
                    const __nv_bfloat16* pa = Ahi + r0 * LDT + kb + ctid * 2;
                    const __nv_bfloat16* qa = Alo + r0 * LDT + kb + ctid * 2;
                    ah[ma][0] = ld32s(pa);
                    ah[ma][1] = ld32s(pa + 8 * LDT);
                    ah[ma][2] = ld32s(pa + 8);
                    ah[ma][3] = ld32s(pa + 8 * LDT + 8);
                    al[ma][0] = ld32s(qa);
                    al[ma][1] = ld32s(qa + 8 * LDT);
                    al[ma][2] = ld32s(qa + 8);
                    al[ma][3] = ld32s(qa + 8 * LDT + 8);
                }
                #pragma unroll
                for (int na = 0; na < 4; na++) {
                    int n0 = wn * 32 + na * 8 + gid;
                    const __nv_bfloat16* pb = Bhi + n0 * LDT + kb + ctid * 2;
                    const __nv_bfloat16* qb = Blo + n0 * LDT + kb + ctid * 2;
                    bh[na][0] = ld32s(pb);
                    bh[na][1] = ld32s(pb + 8);
                    bl[na][0] = ld32s(qb);
                    bl[na][1] = ld32s(qb + 8);
                }
                #pragma unroll
                for (int ma = 0; ma < 2; ma++)
                    #pragma unroll
                    for (int na = 0; na < 4; na++) {
                        mma_bf16(acc[ma][na], ah[ma], bh[na]);
                        mma_bf16(acc[ma][na], ah[ma], bl[na]);
                        mma_bf16(acc[ma][na], al[ma], bh[na]);
                    }
            }
        }

        // ---- commit next chunk to the other buffer
        if (has_next) {
            store_smem(cur ^ 1, aR, bR);
            __syncthreads();
        }
    }

    // ---- epilogue: write fp32 accumulators
    #pragma unroll
    for (int ma = 0; ma < 2; ma++) {
        #pragma unroll
        for (int na = 0; na < 4; na++) {
            size_t rg = rowA0 + wm * 32 + ma * 16 + gid;
            size_t cg = rowB0 + wn * 32 + na * 8 + ctid * 2;
            float2 v0 = make_float2(acc[ma][na][0], acc[ma][na][1]);
            float2 v1 = make_float2(acc[ma][na][2], acc[ma][na][3]);
            *(float2*)&C[rg * (size_t)ldc + cg]       = v0;
            *(float2*)&C[(rg + 8) * (size_t)ldc + cg] = v1;
        }
    }
}

// ---------------------------------------------------------------------------
// LN kernel: raw gates + bias -> nonlinearities -> cell = LN(f*c + i*g),
// writes cell (d_out second half) and s = o*tanh(cell). 1 block / row.
// ---------------------------------------------------------------------------
__device__ __forceinline__ float sigmoidf_(float v) {
    return 1.0f / (1.0f + expf(-v));
}

__global__ __launch_bounds__(256) void ln_kernel(
    const float* __restrict__ cprev,
    const float* __restrict__ bias,
    const float* __restrict__ gamma,
    const float* __restrict__ beta,
    float* __restrict__ out_cell)
{
    const int b = blockIdx.x;
    const int tid = threadIdx.x;
    __shared__ float red[16];

    const size_t gbase = (size_t)b * 2048;
    const size_t hbase = (size_t)b * HDIM;

    float cr[2], og[2];
    #pragma unroll
    for (int e = 0; e < 2; e++) {
        int h = tid + e * 256;
        float ig = sigmoidf_(g_gates[gbase + 0 * 512 + h] + bias[0 * 512 + h]);
        float fg = sigmoidf_(g_gates[gbase + 1 * 512 + h] + bias[1 * 512 + h]);
        float gg = tanhf    (g_gates[gbase + 2 * 512 + h] + bias[2 * 512 + h]);
        og[e]    = sigmoidf_(g_gates[gbase + 3 * 512 + h] + bias[3 * 512 + h]);
        cr[e] = fg * cprev[hbase + h] + ig * gg;
    }

    // mean
    float s = cr[0] + cr[1];
    #pragma unroll
    for (int o = 16; o > 0; o >>= 1) s += __shfl_down_sync(0xffffffffu, s, o);
    if ((tid & 31) == 0) red[tid >> 5] = s;
    __syncthreads();
    if (tid < 32) {
        float t = (tid < 8) ? red[tid] : 0.f;
        #pragma unroll
        for (int o = 4; o > 0; o >>= 1) t += __shfl_down_sync(0xffffffffu, t, o);
        if (tid == 0) red[0] = t;
    }
    __syncthreads();
    const float mu = red[0] * (1.0f / HDIM);
    __syncthreads();

    // variance
    float d0 = cr[0] - mu, d1 = cr[1] - mu;
    float sv = d0 * d0 + d1 * d1;
    #pragma unroll
    for (int o = 16; o > 0; o >>= 1) sv += __shfl_down_sync(0xffffffffu, sv, o);
    if ((tid & 31) == 0) red[tid >> 5] = sv;
    __syncthreads();
    if (tid < 32) {
        float t = (tid < 8) ? red[tid] : 0.f;
        #pragma unroll
        for (int o = 4; o > 0; o >>= 1) t += __shfl_down_sync(0xffffffffu, t, o);
        if (tid == 0) red[0] = t;
    }
    __syncthreads();
    const float rstd = rsqrtf(red[0] * (1.0f / HDIM) + LN_EPS);

    float c0 = d0 * rstd * gamma[tid]       + beta[tid];
    float c1 = d1 * rstd * gamma[tid + 256] + beta[tid + 256];
    out_cell[hbase + tid]       = c0;
    out_cell[hbase + tid + 256] = c1;
    g_s[hbase + tid]       = og[0] * tanhf(c0);
    g_s[hbase + tid + 256] = og[1] * tanhf(c1);
}

// ---------------------------------------------------------------------------
// d_out layout assumption: (out, cell) -> out[B,H] @ 0, cell[B,H] @ B*H.
// If rel_err ~O(1) with sane math, swap the halves next round.
// ---------------------------------------------------------------------------
extern "C" void kernel_launch(void* const* d_in, const int* in_sizes, int n_in,
                              void* d_out, int out_size)
{
    const float* x     = (const float*)d_in[0];
    const float* hprev = (const float*)d_in[1];
    const float* cprev = (const float*)d_in[2];
    const float* W     = (const float*)d_in[3];
    const float* bias  = (const float*)d_in[4];
    const float* gamma = (const float*)d_in[5];
    const float* beta  = (const float*)d_in[6];
    const float* Wp    = (const float*)d_in[7];

    float* out      = (float*)d_out;                       // [B, H]
    float* out_cell = (float*)d_out + (size_t)BSZ * HDIM;  // [B, H]

    float* gates_ptr;
    cudaGetSymbolAddress((void**)&gates_ptr, g_gates);
    float* s_ptr;
    cudaGetSymbolAddress((void**)&s_ptr, g_s);

    cudaFuncSetAttribute(mma_gemm<32, 16>, cudaFuncAttributeMaxDynamicSharedMemorySize, SMEM_BYTES);
    cudaFuncSetAttribute(mma_gemm<16, 16>, cudaFuncAttributeMaxDynamicSharedMemorySize, SMEM_BYTES);

    // GEMM1: gates[B, 2048] = [x | h_prev] @ W^T  (K = 1024, A split at chunk 16)
    dim3 g1(2048 / BN, BSZ / BM);   // 16 x 128
    mma_gemm<32, 16><<<g1, 512, SMEM_BYTES>>>(x, hprev, W, gates_ptr, 1024, 2048);

    // LN + elementwise
    ln_kernel<<<BSZ, 256>>>(cprev, bias, gamma, beta, out_cell);

    // GEMM2: out[B, 512] = s @ Wp^T  (K = 512; SPLIT >= NCHUNK -> always A1)
    dim3 g2(512 / BN, BSZ / BM);    // 4 x 128
    mma_gemm<16, 16><<<g2, 512, SMEM_BYTES>>>(s_ptr, s_ptr, Wp, out, 512, 512);
}

// round 10
// speedup vs baseline: 1.0063x; 1.0063x over previous
#include <cuda_runtime.h>
#include <cuda_bf16.h>
#include <math.h>
#include <stdint.h>

#define BSZ   16384
#define IDIM  512
#define HDIM  512
#define LN_EPS 1e-5f

// ---------------- scratch (device globals: allocation-free) ----------------
__device__ float g_gates[(size_t)BSZ * 2048];  // raw gates pre-bias [B, 4H]
__device__ float g_s[(size_t)BSZ * HDIM];      // o * tanh(LN(cell))

// ---------------------------------------------------------------------------
// mma.sync bf16 GEMM (base ISA, sm_80+). C[M,N] = A[M,K] * B[N,K]^T, fp32
// in/out, bf16x3 split: D += Ahi*Bhi + Ahi*Blo + Alo*Bhi (fp32 accum).
// Block tile 128x128, BK=32, 512 threads = 16 warps (4x4), warp tile 32x32.
// R10: fragment loads via ldmatrix.x4 (16 LDSM/chunk/thread vs 64 LDS.32);
// LDT=40 rows -> LDSM conflict-free ({0,4,..,28} word-starts tile 32 banks).
// ---------------------------------------------------------------------------
#define BM   128
#define BN   128
#define BK   32
#define LDT  40                      // bf16 row stride (32 + 8 pad)
#define TILE_BYTES (128 * LDT * 2)   // 10240 B per tile
#define BUF_BYTES  (4 * TILE_BYTES)  // Ahi,Alo,Bhi,Blo
#define SMEM_BYTES (2 * BUF_BYTES)   // 81920 B double-buffered

__device__ __forceinline__ uint32_t smem_u32(const void* p) {
    uint32_t a;
    asm("{ .reg .u64 t; cvta.to.shared.u64 t, %1; cvt.u32.u64 %0, t; }"
        : "=r"(a) : "l"(p));
    return a;
}

__device__ __forceinline__ void mma_bf16(float* d, const uint32_t* a,
                                         uint32_t b0, uint32_t b1) {
    asm volatile(
        "mma.sync.aligned.m16n8k16.row.col.f32.bf16.bf16.f32 "
        "{%0,%1,%2,%3}, {%4,%5,%6,%7}, {%8,%9}, {%0,%1,%2,%3};\n"
        : "+f"(d[0]), "+f"(d[1]), "+f"(d[2]), "+f"(d[3])
        : "r"(a[0]), "r"(a[1]), "r"(a[2]), "r"(a[3]), "r"(b0), "r"(b1));
}

__device__ __forceinline__ void ldsm_x4(uint32_t* r, uint32_t addr) {
    asm volatile("ldmatrix.sync.aligned.m8n8.x4.shared.b16 {%0,%1,%2,%3}, [%4];"
        : "=r"(r[0]), "=r"(r[1]), "=r"(r[2]), "=r"(r[3]) : "r"(addr));
}

// Split fp32 -> (hi bf16, lo bf16 = bf16(v - float(hi))).
__device__ __forceinline__ void bf16split(float v, uint16_t& hb, uint16_t& lb) {
    __nv_bfloat16 h = __float2bfloat16(v);
    hb = __bfloat16_as_ushort(h);
    lb = __bfloat16_as_ushort(__float2bfloat16(v - __bfloat162float(h)));
}
__device__ __forceinline__ uint32_t pack16(uint16_t a, uint16_t b) {
    return (uint32_t)a | ((uint32_t)b << 16);
}

template <int NCHUNK, int SPLIT>
__global__ __launch_bounds__(512) void mma_gemm(
    const float* __restrict__ A1, const float* __restrict__ A2,
    const float* __restrict__ B,  float* __restrict__ C,
    int ldb, int ldc)
{
    extern __shared__ char smem[];
    const uint32_t sb = smem_u32(smem);

    const int tid  = threadIdx.x;
    const int wid  = tid >> 5;
    const int lane = tid & 31;
    const int wm   = wid >> 2;        // 0..3  (m warp row)
    const int wn   = wid & 3;         // 0..3  (n warp col)
    const int gid  = lane >> 2;       // 0..7
    const int ctid = lane & 3;        // 0..3

    const size_t rowA0 = (size_t)blockIdx.y * BM;
    const size_t rowB0 = (size_t)blockIdx.x * BN;

    // ldmatrix per-lane byte offset within a tile:
    // row = (lane&15), k-col block = (lane>>4)*8 elements.
    const uint32_t lm_off = (uint32_t)(((lane & 15) * LDT + (lane >> 4) * 8) * 2);

    float acc[2][4][4];
    #pragma unroll
    for (int i = 0; i < 2; i++)
        #pragma unroll
        for (int j = 0; j < 4; j++)
            #pragma unroll
            for (int q = 0; q < 4; q++) acc[i][j][q] = 0.f;

    // Loader slots: idx = tid + j*512; row = idx>>3; c4 = idx&7.
    int l_row[2], l_c4[2];
    #pragma unroll
    for (int j = 0; j < 2; j++) {
        int idx = tid + j * 512;
        l_row[j] = idx >> 3;
        l_c4[j]  = idx & 7;
    }

    auto load_regs = [&](int c, float4* aR, float4* bR) {
        const float* Asrc = (c < SPLIT) ? A1 : A2;
        const int ka = (c < SPLIT) ? c * BK : (c - SPLIT) * BK;
        const int kb = c * BK;
        #pragma unroll
        for (int j = 0; j < 2; j++) {
            aR[j] = *(const float4*)&Asrc[(rowA0 + l_row[j]) * 512 + ka + l_c4[j] * 4];
            bR[j] = *(const float4*)&B[(rowB0 + l_row[j]) * (size_t)ldb + kb + l_c4[j] * 4];
        }
    };

    auto store_smem = [&](int buf, const float4* aR, const float4* bR) {
        char* base = smem + buf * BUF_BYTES;
        __nv_bfloat16* Ahi = (__nv_bfloat16*)(base);
        __nv_bfloat16* Alo = (__nv_bfloat16*)(base + TILE_BYTES);
        __nv_bfloat16* Bhi = (__nv_bfloat16*)(base + 2 * TILE_BYTES);
        __nv_bfloat16* Blo = (__nv_bfloat16*)(base + 3 * TILE_BYTES);
        #pragma unroll
        for (int j = 0; j < 2; j++) {
            int off = l_row[j] * LDT + l_c4[j] * 4;
            {
                float4 v = aR[j];
                uint16_t hx, lx, hy, ly, hz, lz, hw, lw;
                bf16split(v.x, hx, lx); bf16split(v.y, hy, ly);
                bf16split(v.z, hz, lz); bf16split(v.w, hw, lw);
                *(uint32_t*)&Ahi[off]     = pack16(hx, hy);
                *(uint32_t*)&Ahi[off + 2] = pack16(hz, hw);
                *(uint32_t*)&Alo[off]     = pack16(lx, ly);
                *(uint32_t*)&Alo[off + 2] = pack16(lz, lw);
            }
            {
                float4 v = bR[j];
                uint16_t hx, lx, hy, ly, hz, lz, hw, lw;
                bf16split(v.x, hx, lx); bf16split(v.y, hy, ly);
                bf16split(v.z, hz, lz); bf16split(v.w, hw, lw);
                *(uint32_t*)&Bhi[off]     = pack16(hx, hy);
                *(uint32_t*)&Bhi[off + 2] = pack16(hz, hw);
                *(uint32_t*)&Blo[off]     = pack16(lx, ly);
                *(uint32_t*)&Blo[off + 2] = pack16(lz, lw);
            }
        }
    };

    // ---- preload chunk 0 into buffer 0
    {
        float4 aR[2], bR[2];
        load_regs(0, aR, bR);
        store_smem(0, aR, bR);
    }
    __syncthreads();

    for (int c = 0; c < NCHUNK; c++) {
        const int cur = c & 1;
        const bool has_next = (c + 1 < NCHUNK);

        // ---- prefetch next chunk into registers
        float4 aR[2], bR[2];
        if (has_next) load_regs(c + 1, aR, bR);

        // ---- compute current buffer (frag loads via ldmatrix.x4)
        {
            const uint32_t base = sb + cur * BUF_BYTES;
            const uint32_t sAhi = base;
            const uint32_t sAlo = base + TILE_BYTES;
            const uint32_t sBhi = base + 2 * TILE_BYTES;
            const uint32_t sBlo = base + 3 * TILE_BYTES;

            const uint32_t aRow = (uint32_t)((wm * 32) * LDT * 2) + lm_off;
            const uint32_t bRow = (uint32_t)((wn * 32) * LDT * 2) + lm_off;

            #pragma unroll
            for (int ks = 0; ks < 2; ks++) {
                const uint32_t kbB = (uint32_t)(ks * 16 * 2);   // k offset bytes
                uint32_t ah[2][4], al[2][4];   // A atoms (ma = 0,1)
                uint32_t bhq[2][4], blq[2][4]; // B quads (pair = 0,1)
                #pragma unroll
                for (int ma = 0; ma < 2; ma++) {
                    uint32_t ro = (uint32_t)(ma * 16 * LDT * 2);
                    ldsm_x4(ah[ma], sAhi + aRow + ro + kbB);
                    ldsm_x4(al[ma], sAlo + aRow + ro + kbB);
                }
                #pragma unroll
                for (int pr = 0; pr < 2; pr++) {
                    uint32_t ro = (uint32_t)(pr * 16 * LDT * 2);
                    ldsm_x4(bhq[pr], sBhi + bRow + ro + kbB);
                    ldsm_x4(blq[pr], sBlo + bRow + ro + kbB);
                }
                // B atom na: pair = na>>1, sub = na&1 -> {q[sub], q[sub+2]}
                #pragma unroll
                for (int ma = 0; ma < 2; ma++)
                    #pragma unroll
                    for (int na = 0; na < 4; na++) {
                        const int pr = na >> 1, sub = na & 1;
                        mma_bf16(acc[ma][na], ah[ma], bhq[pr][sub], bhq[pr][sub + 2]);
                        mma_bf16(acc[ma][na], ah[ma], blq[pr][sub], blq[pr][sub + 2]);
                        mma_bf16(acc[ma][na], al[ma], bhq[pr][sub], bhq[pr][sub + 2]);
                    }
            }
        }

        // ---- commit next chunk to the other buffer
        if (has_next) {
            store_smem(cur ^ 1, aR, bR);
            __syncthreads();
        }
    }

    // ---- epilogue: write fp32 accumulators
    #pragma unroll
    for (int ma = 0; ma < 2; ma++) {
        #pragma unroll
        for (int na = 0; na < 4; na++) {
            size_t rg = rowA0 + wm * 32 + ma * 16 + gid;
            size_t cg = rowB0 + wn * 32 + na * 8 + ctid * 2;
            float2 v0 = make_float2(acc[ma][na][0], acc[ma][na][1]);
            float2 v1 = make_float2(acc[ma][na][2], acc[ma][na][3]);
            *(float2*)&C[rg * (size_t)ldc + cg]       = v0;
            *(float2*)&C[(rg + 8) * (size_t)ldc + cg] = v1;
        }
    }
}

// ---------------------------------------------------------------------------
// LN kernel: raw gates + bias -> nonlinearities -> cell = LN(f*c + i*g),
// writes cell (d_out second half) and s = o*tanh(cell). 1 block / row.
// ---------------------------------------------------------------------------
__device__ __forceinline__ float sigmoidf_(float v) {
    return 1.0f / (1.0f + expf(-v));
}

__global__ __launch_bounds__(256) void ln_kernel(
    const float* __restrict__ cprev,
    const float* __restrict__ bias,
    const float* __restrict__ gamma,
    const float* __restrict__ beta,
    float* __restrict__ out_cell)
{
    const int b = blockIdx.x;
    const int tid = threadIdx.x;
    __shared__ float red[16];

    const size_t gbase = (size_t)b * 2048;
    const size_t hbase = (size_t)b * HDIM;

    float cr[2], og[2];
    #pragma unroll
    for (int e = 0; e < 2; e++) {
        int h = tid + e * 256;
        float ig = sigmoidf_(g_gates[gbase + 0 * 512 + h] + bias[0 * 512 + h]);
        float fg = sigmoidf_(g_gates[gbase + 1 * 512 + h] + bias[1 * 512 + h]);
        float gg = tanhf    (g_gates[gbase + 2 * 512 + h] + bias[2 * 512 + h]);
        og[e]    = sigmoidf_(g_gates[gbase + 3 * 512 + h] + bias[3 * 512 + h]);
        cr[e] = fg * cprev[hbase + h] + ig * gg;
    }

    // mean
    float s = cr[0] + cr[1];
    #pragma unroll
    for (int o = 16; o > 0; o >>= 1) s += __shfl_down_sync(0xffffffffu, s, o);
    if ((tid & 31) == 0) red[tid >> 5] = s;
    __syncthreads();
    if (tid < 32) {
        float t = (tid < 8) ? red[tid] : 0.f;
        #pragma unroll
        for (int o = 4; o > 0; o >>= 1) t += __shfl_down_sync(0xffffffffu, t, o);
        if (tid == 0) red[0] = t;
    }
    __syncthreads();
    const float mu = red[0] * (1.0f / HDIM);
    __syncthreads();

    // variance
    float d0 = cr[0] - mu, d1 = cr[1] - mu;
    float sv = d0 * d0 + d1 * d1;
    #pragma unroll
    for (int o = 16; o > 0; o >>= 1) sv += __shfl_down_sync(0xffffffffu, sv, o);
    if ((tid & 31) == 0) red[tid >> 5] = sv;
    __syncthreads();
    if (tid < 32) {
        float t = (tid < 8) ? red[tid] : 0.f;
        #pragma unroll
        for (int o = 4; o > 0; o >>= 1) t += __shfl_down_sync(0xffffffffu, t, o);
        if (tid == 0) red[0] = t;
    }
    __syncthreads();
    const float rstd = rsqrtf(red[0] * (1.0f / HDIM) + LN_EPS);

    float c0 = d0 * rstd * gamma[tid]       + beta[tid];
    float c1 = d1 * rstd * gamma[tid + 256] + beta[tid + 256];
    out_cell[hbase + tid]       = c0;
    out_cell[hbase + tid + 256] = c1;
    g_s[hbase + tid]       = og[0] * tanhf(c0);
    g_s[hbase + tid + 256] = og[1] * tanhf(c1);
}

// ---------------------------------------------------------------------------
extern "C" void kernel_launch(void* const* d_in, const int* in_sizes, int n_in,
                              void* d_out, int out_size)
{
    const float* x     = (const float*)d_in[0];
    const float* hprev = (const float*)d_in[1];
    const float* cprev = (const float*)d_in[2];
    const float* W     = (const float*)d_in[3];
    const float* bias  = (const float*)d_in[4];
    const float* gamma = (const float*)d_in[5];
    const float* beta  = (const float*)d_in[6];
    const float* Wp    = (const float*)d_in[7];

    float* out      = (float*)d_out;                       // [B, H]
    float* out_cell = (float*)d_out + (size_t)BSZ * HDIM;  // [B, H]

    float* gates_ptr;
    cudaGetSymbolAddress((void**)&gates_ptr, g_gates);
    float* s_ptr;
    cudaGetSymbolAddress((void**)&s_ptr, g_s);

    cudaFuncSetAttribute(mma_gemm<32, 16>, cudaFuncAttributeMaxDynamicSharedMemorySize, SMEM_BYTES);
    cudaFuncSetAttribute(mma_gemm<16, 16>, cudaFuncAttributeMaxDynamicSharedMemorySize, SMEM_BYTES);

    // GEMM1: gates[B, 2048] = [x | h_prev] @ W^T  (K = 1024, A split at chunk 16)
    dim3 g1(2048 / BN, BSZ / BM);   // 16 x 128
    mma_gemm<32, 16><<<g1, 512, SMEM_BYTES>>>(x, hprev, W, gates_ptr, 1024, 2048);

    // LN + elementwise
    ln_kernel<<<BSZ, 256>>>(cprev, bias, gamma, beta, out_cell);

    // GEMM2: out[B, 512] = s @ Wp^T  (K = 512; SPLIT >= NCHUNK -> always A1)
    dim3 g2(512 / BN, BSZ / BM);    // 4 x 128
    mma_gemm<16, 16><<<g2, 512, SMEM_BYTES>>>(s_ptr, s_ptr, Wp, out, 512, 512);
}

// round 11
// speedup vs baseline: 1.0520x; 1.0454x over previous
#include <cuda_runtime.h>
#include <cuda_bf16.h>
#include <math.h>
#include <stdint.h>

#define BSZ   16384
#define IDIM  512
#define HDIM  512
#define LN_EPS 1e-5f

// ---------------- scratch (device globals: allocation-free) ----------------
__device__ float g_gates[(size_t)BSZ * 2048];            // raw gates pre-bias
__device__ __nv_bfloat16 g_chi[(size_t)BSZ * 1024];      // combined [x|h] hi
__device__ __nv_bfloat16 g_clo[(size_t)BSZ * 1024];      // combined lo
__device__ __nv_bfloat16 g_whi[(size_t)2048 * 1024];     // W hi
__device__ __nv_bfloat16 g_wlo[(size_t)2048 * 1024];     // W lo
__device__ __nv_bfloat16 g_wphi[(size_t)512 * 512];      // Wp hi
__device__ __nv_bfloat16 g_wplo[(size_t)512 * 512];      // Wp lo
__device__ __nv_bfloat16 g_shi[(size_t)BSZ * 512];       // s hi
__device__ __nv_bfloat16 g_slo[(size_t)BSZ * 512];       // s lo

// ---------------- helpers --------------------------------------------------
__device__ __forceinline__ uint32_t smem_u32(const void* p) {
    uint32_t a;
    asm("{ .reg .u64 t; cvta.to.shared.u64 t, %1; cvt.u32.u64 %0, t; }"
        : "=r"(a) : "l"(p));
    return a;
}
__device__ __forceinline__ void bf16split(float v, uint16_t& hb, uint16_t& lb) {
    __nv_bfloat16 h = __float2bfloat16(v);
    hb = __bfloat16_as_ushort(h);
    lb = __bfloat16_as_ushort(__float2bfloat16(v - __bfloat162float(h)));
}
__device__ __forceinline__ uint32_t pack16(uint16_t a, uint16_t b) {
    return (uint32_t)a | ((uint32_t)b << 16);
}
__device__ __forceinline__ void mma_bf16(float* d, const uint32_t* a,
                                         uint32_t b0, uint32_t b1) {
    asm volatile(
        "mma.sync.aligned.m16n8k16.row.col.f32.bf16.bf16.f32 "
        "{%0,%1,%2,%3}, {%4,%5,%6,%7}, {%8,%9}, {%0,%1,%2,%3};\n"
        : "+f"(d[0]), "+f"(d[1]), "+f"(d[2]), "+f"(d[3])
        : "r"(a[0]), "r"(a[1]), "r"(a[2]), "r"(a[3]), "r"(b0), "r"(b1));
}
__device__ __forceinline__ void ldsm_x4(uint32_t* r, uint32_t addr) {
    asm volatile("ldmatrix.sync.aligned.m8n8.x4.shared.b16 {%0,%1,%2,%3}, [%4];"
        : "=r"(r[0]), "=r"(r[1]), "=r"(r[2]), "=r"(r[3]) : "r"(addr));
}
__device__ __forceinline__ void cp_async16(uint32_t saddr, const void* g) {
    asm volatile("cp.async.cg.shared.global [%0], [%1], 16;\n"
                 :: "r"(saddr), "l"(g) : "memory");
}
#define CP_COMMIT() asm volatile("cp.async.commit_group;\n" ::: "memory")
template <int N> __device__ __forceinline__ void cp_wait() {
    asm volatile("cp.async.wait_group %0;\n" :: "n"(N) : "memory");
}

// ---------------------------------------------------------------------------
// Pre-pass: fp32 -> bf16 hi/lo splits (one-time, bandwidth-bound).
// ---------------------------------------------------------------------------
__global__ __launch_bounds__(256) void conv_combined_kernel(
    const float* __restrict__ x, const float* __restrict__ h)
{
    int idx = blockIdx.x * 256 + threadIdx.x;      // B*256 threads, 1 float4 each
    int row = idx >> 8;
    int c4  = idx & 255;
    const float* src = (c4 < 128) ? x + (size_t)row * 512 + c4 * 4
                                  : h + (size_t)row * 512 + (c4 - 128) * 4;
    float4 v = *(const float4*)src;
    uint16_t hx, lx, hy, ly, hz, lz, hw, lw;
    bf16split(v.x, hx, lx); bf16split(v.y, hy, ly);
    bf16split(v.z, hz, lz); bf16split(v.w, hw, lw);
    size_t o = (size_t)row * 1024 + c4 * 4;
    *(uint2*)&g_chi[o] = make_uint2(pack16(hx, hy), pack16(hz, hw));
    *(uint2*)&g_clo[o] = make_uint2(pack16(lx, ly), pack16(lz, lw));
}

__global__ __launch_bounds__(256) void conv_mat_kernel(
    const float* __restrict__ src, __nv_bfloat16* __restrict__ hi,
    __nv_bfloat16* __restrict__ lo, int n4)
{
    int idx = blockIdx.x * 256 + threadIdx.x;
    if (idx >= n4) return;
    float4 v = ((const float4*)src)[idx];
    uint16_t hx, lx, hy, ly, hz, lz, hw, lw;
    bf16split(v.x, hx, lx); bf16split(v.y, hy, ly);
    bf16split(v.z, hz, lz); bf16split(v.w, hw, lw);
    *(uint2*)&hi[(size_t)idx * 4] = make_uint2(pack16(hx, hy), pack16(hz, hw));
    *(uint2*)&lo[(size_t)idx * 4] = make_uint2(pack16(lx, ly), pack16(lz, lw));
}

// ---------------------------------------------------------------------------
// mma.sync bf16 GEMM, inputs pre-split to bf16 hi/lo in gmem.
// C[M,N] = A[M,K] * B[N,K]^T; D += Ahi*Bhi + Ahi*Blo + Alo*Bhi (fp32 accum).
// Block 128x128, BK=32, 512 thr = 16 warps (4x4), warp tile 32x32.
// gmem->smem via cp.async (no cvt / STS in warp stream), 2-stage pipeline.
// ---------------------------------------------------------------------------
#define BM   128
#define BN   128
#define BK   32
#define LDT  40                      // bf16 row stride (32 + 8 pad)
#define TILE_BYTES (128 * LDT * 2)   // 10240 B
#define BUF_BYTES  (4 * TILE_BYTES)  // Ahi,Alo,Bhi,Blo
#define SMEM_BYTES (2 * BUF_BYTES)   // 81920 B

template <int NCHUNK>
__global__ __launch_bounds__(512) void mma_gemm(
    const __nv_bfloat16* __restrict__ Ahi_g, const __nv_bfloat16* __restrict__ Alo_g,
    const __nv_bfloat16* __restrict__ Bhi_g, const __nv_bfloat16* __restrict__ Blo_g,
    float* __restrict__ C, int lda, int ldc)
{
    extern __shared__ char smem[];
    const uint32_t sb = smem_u32(smem);

    const int tid  = threadIdx.x;
    const int wid  = tid >> 5;
    const int lane = tid & 31;
    const int wm   = wid >> 2;
    const int wn   = wid & 3;
    const int gid  = lane >> 2;
    const int ctid = lane & 3;

    const size_t rowA0 = (size_t)blockIdx.y * BM;
    const size_t rowB0 = (size_t)blockIdx.x * BN;

    // cp.async slot: 512 threads x 16B cover one 128x32 bf16 tile exactly.
    const int l_row = tid >> 2;
    const int l_c8  = (tid & 3) * 8;
    const uint32_t sdst = (uint32_t)((l_row * LDT + l_c8) * 2);

    // ldmatrix lane offset: row = lane&15, k-block = (lane>>4)*8 elements.
    const uint32_t lm_off = (uint32_t)(((lane & 15) * LDT + (lane >> 4) * 8) * 2);

    float acc[2][4][4];
    #pragma unroll
    for (int i = 0; i < 2; i++)
        #pragma unroll
        for (int j = 0; j < 4; j++)
            #pragma unroll
            for (int q = 0; q < 4; q++) acc[i][j][q] = 0.f;

    auto issue = [&](int c, int buf) {
        const uint32_t base = sb + buf * BUF_BYTES;
        const size_t ga = (rowA0 + l_row) * (size_t)lda + c * BK + l_c8;
        const size_t gb = (rowB0 + l_row) * (size_t)lda + c * BK + l_c8;
        cp_async16(base + sdst,                  Ahi_g + ga);
        cp_async16(base + TILE_BYTES + sdst,     Alo_g + ga);
        cp_async16(base + 2 * TILE_BYTES + sdst, Bhi_g + gb);
        cp_async16(base + 3 * TILE_BYTES + sdst, Blo_g + gb);
    };

    issue(0, 0);
    CP_COMMIT();

    for (int c = 0; c < NCHUNK; c++) {
        const int cur = c & 1;
        const bool has_next = (c + 1 < NCHUNK);

        if (has_next) { issue(c + 1, cur ^ 1); CP_COMMIT(); }
        if (has_next) cp_wait<1>(); else cp_wait<0>();
        __syncthreads();

        // ---- compute current buffer (LDSM + HMMA only)
        {
            const uint32_t base = sb + cur * BUF_BYTES;
            const uint32_t sAhi = base;
            const uint32_t sAlo = base + TILE_BYTES;
            const uint32_t sBhi = base + 2 * TILE_BYTES;
            const uint32_t sBlo = base + 3 * TILE_BYTES;

            const uint32_t aRow = (uint32_t)((wm * 32) * LDT * 2) + lm_off;
            const uint32_t bRow = (uint32_t)((wn * 32) * LDT * 2) + lm_off;

            #pragma unroll
            for (int ks = 0; ks < 2; ks++) {
                const uint32_t kbB = (uint32_t)(ks * 16 * 2);
                uint32_t ah[2][4], al[2][4], bhq[2][4], blq[2][4];
                #pragma unroll
                for (int ma = 0; ma < 2; ma++) {
                    uint32_t ro = (uint32_t)(ma * 16 * LDT * 2);
                    ldsm_x4(ah[ma], sAhi + aRow + ro + kbB);
                    ldsm_x4(al[ma], sAlo + aRow + ro + kbB);
                }
                #pragma unroll
                for (int pr = 0; pr < 2; pr++) {
                    uint32_t ro = (uint32_t)(pr * 16 * LDT * 2);
                    ldsm_x4(bhq[pr], sBhi + bRow + ro + kbB);
                    ldsm_x4(blq[pr], sBlo + bRow + ro + kbB);
                }
                #pragma unroll
                for (int ma = 0; ma < 2; ma++)
                    #pragma unroll
                    for (int na = 0; na < 4; na++) {
                        const int pr = na >> 1, sub = na & 1;
                        mma_bf16(acc[ma][na], ah[ma], bhq[pr][sub], bhq[pr][sub + 2]);
                        mma_bf16(acc[ma][na], ah[ma], blq[pr][sub], blq[pr][sub + 2]);
                        mma_bf16(acc[ma][na], al[ma], bhq[pr][sub], bhq[pr][sub + 2]);
                    }
            }
        }
        __syncthreads();   // compute done before next iter's cp.async overwrites
    }

    // ---- epilogue
    #pragma unroll
    for (int ma = 0; ma < 2; ma++) {
        #pragma unroll
        for (int na = 0; na < 4; na++) {
            size_t rg = rowA0 + wm * 32 + ma * 16 + gid;
            size_t cg = rowB0 + wn * 32 + na * 8 + ctid * 2;
            float2 v0 = make_float2(acc[ma][na][0], acc[ma][na][1]);
            float2 v1 = make_float2(acc[ma][na][2], acc[ma][na][3]);
            *(float2*)&C[rg * (size_t)ldc + cg]       = v0;
            *(float2*)&C[(rg + 8) * (size_t)ldc + cg] = v1;
        }
    }
}

// ---------------------------------------------------------------------------
// LN kernel: gates + bias -> cell = LN(f*c + i*g); writes cell (d_out 2nd
// half) and s = o*tanh(cell) pre-split to bf16 hi/lo for GEMM2.
// ---------------------------------------------------------------------------
__device__ __forceinline__ float sigmoidf_(float v) {
    return 1.0f / (1.0f + expf(-v));
}

__global__ __launch_bounds__(256) void ln_kernel(
    const float* __restrict__ cprev,
    const float* __restrict__ bias,
    const float* __restrict__ gamma,
    const float* __restrict__ beta,
    float* __restrict__ out_cell)
{
    const int b = blockIdx.x;
    const int tid = threadIdx.x;
    __shared__ float red[16];

    const size_t gbase = (size_t)b * 2048;
    const size_t hbase = (size_t)b * HDIM;

    float cr[2], og[2];
    #pragma unroll
    for (int e = 0; e < 2; e++) {
        int h = tid + e * 256;
        float ig = sigmoidf_(g_gates[gbase + 0 * 512 + h] + bias[0 * 512 + h]);
        float fg = sigmoidf_(g_gates[gbase + 1 * 512 + h] + bias[1 * 512 + h]);
        float gg = tanhf    (g_gates[gbase + 2 * 512 + h] + bias[2 * 512 + h]);
        og[e]    = sigmoidf_(g_gates[gbase + 3 * 512 + h] + bias[3 * 512 + h]);
        cr[e] = fg * cprev[hbase + h] + ig * gg;
    }

    float s = cr[0] + cr[1];
    #pragma unroll
    for (int o = 16; o > 0; o >>= 1) s += __shfl_down_sync(0xffffffffu, s, o);
    if ((tid & 31) == 0) red[tid >> 5] = s;
    __syncthreads();
    if (tid < 32) {
        float t = (tid < 8) ? red[tid] : 0.f;
        #pragma unroll
        for (int o = 4; o > 0; o >>= 1) t += __shfl_down_sync(0xffffffffu, t, o);
        if (tid == 0) red[0] = t;
    }
    __syncthreads();
    const float mu = red[0] * (1.0f / HDIM);
    __syncthreads();

    float d0 = cr[0] - mu, d1 = cr[1] - mu;
    float sv = d0 * d0 + d1 * d1;
    #pragma unroll
    for (int o = 16; o > 0; o >>= 1) sv += __shfl_down_sync(0xffffffffu, sv, o);
    if ((tid & 31) == 0) red[tid >> 5] = sv;
    __syncthreads();
    if (tid < 32) {
        float t = (tid < 8) ? red[tid] : 0.f;
        #pragma unroll
        for (int o = 4; o > 0; o >>= 1) t += __shfl_down_sync(0xffffffffu, t, o);
        if (tid == 0) red[0] = t;
    }
    __syncthreads();
    const float rstd = rsqrtf(red[0] * (1.0f / HDIM) + LN_EPS);

    #pragma unroll
    for (int e = 0; e < 2; e++) {
        int h = tid + e * 256;
        float d = (e == 0) ? d0 : d1;
        float cell = d * rstd * gamma[h] + beta[h];
        out_cell[hbase + h] = cell;
        float sval = og[e] * tanhf(cell);
        uint16_t hb, lb;
        bf16split(sval, hb, lb);
        *(uint16_t*)&g_shi[hbase + h] = hb;
        *(uint16_t*)&g_slo[hbase + h] = lb;
    }
}

// ---------------------------------------------------------------------------
extern "C" void kernel_launch(void* const* d_in, const int* in_sizes, int n_in,
                              void* d_out, int out_size)
{
    const float* x     = (const float*)d_in[0];
    const float* hprev = (const float*)d_in[1];
    const float* cprev = (const float*)d_in[2];
    const float* W     = (const float*)d_in[3];
    const float* bias  = (const float*)d_in[4];
    const float* gamma = (const float*)d_in[5];
    const float* beta  = (const float*)d_in[6];
    const float* Wp    = (const float*)d_in[7];

    float* out      = (float*)d_out;                       // [B, H]
    float* out_cell = (float*)d_out + (size_t)BSZ * HDIM;  // [B, H]

    float* gates_ptr;
    cudaGetSymbolAddress((void**)&gates_ptr, g_gates);
    __nv_bfloat16 *chi, *clo, *whi, *wlo, *wphi, *wplo, *shi, *slo;
    cudaGetSymbolAddress((void**)&chi,  g_chi);
    cudaGetSymbolAddress((void**)&clo,  g_clo);
    cudaGetSymbolAddress((void**)&whi,  g_whi);
    cudaGetSymbolAddress((void**)&wlo,  g_wlo);
    cudaGetSymbolAddress((void**)&wphi, g_wphi);
    cudaGetSymbolAddress((void**)&wplo, g_wplo);
    cudaGetSymbolAddress((void**)&shi,  g_shi);
    cudaGetSymbolAddress((void**)&slo,  g_slo);

    cudaFuncSetAttribute(mma_gemm<32>, cudaFuncAttributeMaxDynamicSharedMemorySize, SMEM_BYTES);
    cudaFuncSetAttribute(mma_gemm<16>, cudaFuncAttributeMaxDynamicSharedMemorySize, SMEM_BYTES);

    // Pre-pass conversions
    conv_combined_kernel<<<BSZ, 256>>>(x, hprev);                        // 4.19M float4
    conv_mat_kernel<<<(2048 * 1024 / 4 + 255) / 256, 256>>>(W,  whi,  wlo,  2048 * 1024 / 4);
    conv_mat_kernel<<<(512 * 512 / 4 + 255) / 256, 256>>>(Wp, wphi, wplo, 512 * 512 / 4);

    // GEMM1: gates[B, 2048] = combined @ W^T  (K = 1024)
    dim3 g1(2048 / BN, BSZ / BM);   // 16 x 128
    mma_gemm<32><<<g1, 512, SMEM_BYTES>>>(chi, clo, whi, wlo, gates_ptr, 1024, 2048);

    // LN + elementwise (+ bf16 split of s)
    ln_kernel<<<BSZ, 256>>>(cprev, bias, gamma, beta, out_cell);

    // GEMM2: out[B, 512] = s @ Wp^T  (K = 512)
    dim3 g2(512 / BN, BSZ / BM);    // 4 x 128
    mma_gemm<16><<<g2, 512, SMEM_BYTES>>>(shi, slo, wphi, wplo, out, 512, 512);
}

// round 16
// speedup vs baseline: 1.1486x; 1.0918x over previous
#include <cuda_runtime.h>
#include <cuda_bf16.h>
#include <math.h>
#include <stdint.h>

#define BSZ   16384
#define IDIM  512
#define HDIM  512
#define LN_EPS 1e-5f

// ---------------- scratch (device globals: allocation-free) ----------------
__device__ float g_gates[(size_t)BSZ * 2048];            // raw gates pre-bias
__device__ __nv_bfloat16 g_chi[(size_t)BSZ * 1024];      // combined [x|h] hi
__device__ __nv_bfloat16 g_clo[(size_t)BSZ * 1024];      // combined lo
__device__ __nv_bfloat16 g_whi[(size_t)2048 * 1024];     // W hi
__device__ __nv_bfloat16 g_wlo[(size_t)2048 * 1024];     // W lo
__device__ __nv_bfloat16 g_wphi[(size_t)512 * 512];      // Wp hi
__device__ __nv_bfloat16 g_wplo[(size_t)512 * 512];      // Wp lo
__device__ __nv_bfloat16 g_shi[(size_t)BSZ * 512];       // s hi
__device__ __nv_bfloat16 g_slo[(size_t)BSZ * 512];       // s lo

// ---------------- helpers --------------------------------------------------
__device__ __forceinline__ uint32_t smem_u32(const void* p) {
    uint32_t a;
    asm("{ .reg .u64 t; cvta.to.shared.u64 t, %1; cvt.u32.u64 %0, t; }"
        : "=r"(a) : "l"(p));
    return a;
}
__device__ __forceinline__ void bf16split(float v, uint16_t& hb, uint16_t& lb) {
    __nv_bfloat16 h = __float2bfloat16(v);
    hb = __bfloat16_as_ushort(h);
    lb = __bfloat16_as_ushort(__float2bfloat16(v - __bfloat162float(h)));
}
__device__ __forceinline__ uint32_t pack16(uint16_t a, uint16_t b) {
    return (uint32_t)a | ((uint32_t)b << 16);
}
__device__ __forceinline__ void mma_bf16(float* d, const uint32_t* a,
                                         uint32_t b0, uint32_t b1) {
    asm volatile(
        "mma.sync.aligned.m16n8k16.row.col.f32.bf16.bf16.f32 "
        "{%0,%1,%2,%3}, {%4,%5,%6,%7}, {%8,%9}, {%0,%1,%2,%3};\n"
        : "+f"(d[0]), "+f"(d[1]), "+f"(d[2]), "+f"(d[3])
        : "r"(a[0]), "r"(a[1]), "r"(a[2]), "r"(a[3]), "r"(b0), "r"(b1));
}
__device__ __forceinline__ void ldsm_x4(uint32_t* r, uint32_t addr) {
    asm volatile("ldmatrix.sync.aligned.m8n8.x4.shared.b16 {%0,%1,%2,%3}, [%4];"
        : "=r"(r[0]), "=r"(r[1]), "=r"(r[2]), "=r"(r[3]) : "r"(addr));
}
__device__ __forceinline__ void cp_async16(uint32_t saddr, const void* g) {
    asm volatile("cp.async.cg.shared.global [%0], [%1], 16;\n"
                 :: "r"(saddr), "l"(g) : "memory");
}
#define CP_COMMIT() asm volatile("cp.async.commit_group;\n" ::: "memory")
template <int N> __device__ __forceinline__ void cp_wait() {
    asm volatile("cp.async.wait_group %0;\n" :: "n"(N) : "memory");
}

// ---------------------------------------------------------------------------
// Pre-pass: fp32 -> bf16 hi/lo splits (one-time, bandwidth-bound).
// ---------------------------------------------------------------------------
__global__ __launch_bounds__(256) void conv_combined_kernel(
    const float* __restrict__ x, const float* __restrict__ h)
{
    int idx = blockIdx.x * 256 + threadIdx.x;
    int row = idx >> 8;
    int c4  = idx & 255;
    const float* src = (c4 < 128) ? x + (size_t)row * 512 + c4 * 4
                                  : h + (size_t)row * 512 + (c4 - 128) * 4;
    float4 v = *(const float4*)src;
    uint16_t hx, lx, hy, ly, hz, lz, hw, lw;
    bf16split(v.x, hx, lx); bf16split(v.y, hy, ly);
    bf16split(v.z, hz, lz); bf16split(v.w, hw, lw);
    size_t o = (size_t)row * 1024 + c4 * 4;
    *(uint2*)&g_chi[o] = make_uint2(pack16(hx, hy), pack16(hz, hw));
    *(uint2*)&g_clo[o] = make_uint2(pack16(lx, ly), pack16(lz, lw));
}

__global__ __launch_bounds__(256) void conv_mat_kernel(
    const float* __restrict__ src, __nv_bfloat16* __restrict__ hi,
    __nv_bfloat16* __restrict__ lo, int n4)
{
    int idx = blockIdx.x * 256 + threadIdx.x;
    if (idx >= n4) return;
    float4 v = ((const float4*)src)[idx];
    uint16_t hx, lx, hy, ly, hz, lz, hw, lw;
    bf16split(v.x, hx, lx); bf16split(v.y, hy, ly);
    bf16split(v.z, hz, lz); bf16split(v.w, hw, lw);
    *(uint2*)&hi[(size_t)idx * 4] = make_uint2(pack16(hx, hy), pack16(hz, hw));
    *(uint2*)&lo[(size_t)idx * 4] = make_uint2(pack16(lx, ly), pack16(lz, lw));
}

// ---------------------------------------------------------------------------
// mma.sync bf16 GEMM, pre-split bf16 hi/lo inputs.
// C[M,N] = A[M,K] * B[N,K]^T; D += Ahi*Bhi + Ahi*Blo + Alo*Bhi (fp32 accum).
// 256 threads = 8 warps (2x4), warp tile 64x32 (4 m-atoms x 4 n-atoms),
// __launch_bounds__(256,2) -> 2 CTAs/SM so barrier/wait bubbles are hidden
// by the co-resident CTA. MMA:LDSM ratio 4:1.
// ---------------------------------------------------------------------------
#define BM   128
#define BN   128
#define BK   32
#define LDT  40
#define TILE_BYTES (128 * LDT * 2)   // 10240 B
#define BUF_BYTES  (4 * TILE_BYTES)
#define SMEM_BYTES (2 * BUF_BYTES)   // 81920 B

template <int NCHUNK>
__global__ __launch_bounds__(256, 2) void mma_gemm(
    const __nv_bfloat16* __restrict__ Ahi_g, const __nv_bfloat16* __restrict__ Alo_g,
    const __nv_bfloat16* __restrict__ Bhi_g, const __nv_bfloat16* __restrict__ Blo_g,
    float* __restrict__ C, int lda, int ldc)
{
    extern __shared__ char smem[];
    const uint32_t sb = smem_u32(smem);

    const int tid  = threadIdx.x;
    const int wid  = tid >> 5;
    const int lane = tid & 31;
    const int wm   = wid >> 2;        // 0..1  (64 m-rows each)
    const int wn   = wid & 3;         // 0..3  (32 n-cols each)
    const int gid  = lane >> 2;
    const int ctid = lane & 3;

    const size_t rowA0 = (size_t)blockIdx.y * BM;
    const size_t rowB0 = (size_t)blockIdx.x * BN;

    // cp.async slots: 256 threads x 2 x 16B cover one 128x32 bf16 tile.
    int l_row[2], l_c8[2];
    uint32_t sdst[2];
    #pragma unroll
    for (int j = 0; j < 2; j++) {
        int idx = tid + j * 256;
        l_row[j] = idx >> 2;
        l_c8[j]  = (idx & 3) * 8;
        sdst[j]  = (uint32_t)((l_row[j] * LDT + l_c8[j]) * 2);
    }

    // ldmatrix lane offset: row = lane&15, k-block = (lane>>4)*8 elements.
    const uint32_t lm_off = (uint32_t)(((lane & 15) * LDT + (lane >> 4) * 8) * 2);

    float acc[4][4][4];
    #pragma unroll
    for (int i = 0; i < 4; i++)
        #pragma unroll
        for (int j = 0; j < 4; j++)
            #pragma unroll
            for (int q = 0; q < 4; q++) acc[i][j][q] = 0.f;

    auto issue = [&](int c, int buf) {
        const uint32_t base = sb + buf * BUF_BYTES;
        #pragma unroll
        for (int j = 0; j < 2; j++) {
            const size_t ga = (rowA0 + l_row[j]) * (size_t)lda + c * BK + l_c8[j];
            const size_t gb = (rowB0 + l_row[j]) * (size_t)lda + c * BK + l_c8[j];
            cp_async16(base + sdst[j],                  Ahi_g + ga);
            cp_async16(base + TILE_BYTES + sdst[j],     Alo_g + ga);
            cp_async16(base + 2 * TILE_BYTES + sdst[j], Bhi_g + gb);
            cp_async16(base + 3 * TILE_BYTES + sdst[j], Blo_g + gb);
        }
    };

    issue(0, 0);
    CP_COMMIT();

    for (int c = 0; c < NCHUNK; c++) {
        const int cur = c & 1;
        const bool has_next = (c + 1 < NCHUNK);

        if (has_next) { issue(c + 1, cur ^ 1); CP_COMMIT(); }
        if (has_next) cp_wait<1>(); else cp_wait<0>();
        __syncthreads();

        // ---- compute current buffer (LDSM + HMMA only)
        {
            const uint32_t base = sb + cur * BUF_BYTES;
            const uint32_t sAhi = base;
            const uint32_t sAlo = base + TILE_BYTES;
            const uint32_t sBhi = base + 2 * TILE_BYTES;
            const uint32_t sBlo = base + 3 * TILE_BYTES;

            const uint32_t aRow = (uint32_t)((wm * 64) * LDT * 2) + lm_off;
            const uint32_t bRow = (uint32_t)((wn * 32) * LDT * 2) + lm_off;

            #pragma unroll
            for (int ks = 0; ks < 2; ks++) {
                const uint32_t kbB = (uint32_t)(ks * 16 * 2);
                uint32_t ah[4][4], al[4][4], bhq[2][4], blq[2][4];
                #pragma unroll
                for (int ma = 0; ma < 4; ma++) {
                    uint32_t ro = (uint32_t)(ma * 16 * LDT * 2);
                    ldsm_x4(ah[ma], sAhi + aRow + ro + kbB);
                    ldsm_x4(al[ma], sAlo + aRow + ro + kbB);
                }
                #pragma unroll
                for (int pr = 0; pr < 2; pr++) {
                    uint32_t ro = (uint32_t)(pr * 16 * LDT * 2);
                    ldsm_x4(bhq[pr], sBhi + bRow + ro + kbB);
                    ldsm_x4(blq[pr], sBlo + bRow + ro + kbB);
                }
                #pragma unroll
                for (int ma = 0; ma < 4; ma++)
                    #pragma unroll
                    for (int na = 0; na < 4; na++) {
                        const int pr = na >> 1, sub = na & 1;
                        mma_bf16(acc[ma][na], ah[ma], bhq[pr][sub], bhq[pr][sub + 2]);
                        mma_bf16(acc[ma][na], ah[ma], blq[pr][sub], blq[pr][sub + 2]);
                        mma_bf16(acc[ma][na], al[ma], bhq[pr][sub], bhq[pr][sub + 2]);
                    }
            }
        }
        __syncthreads();   // compute done before next iter's cp.async overwrites
    }

    // ---- epilogue
    #pragma unroll
    for (int ma = 0; ma < 4; ma++) {
        #pragma unroll
        for (int na = 0; na < 4; na++) {
            size_t rg = rowA0 + wm * 64 + ma * 16 + gid;
            size_t cg = rowB0 + wn * 32 + na * 8 + ctid * 2;
            float2 v0 = make_float2(acc[ma][na][0], acc[ma][na][1]);
            float2 v1 = make_float2(acc[ma][na][2], acc[ma][na][3]);
            *(float2*)&C[rg * (size_t)ldc + cg]       = v0;
            *(float2*)&C[(rg + 8) * (size_t)ldc + cg] = v1;
        }
    }
}

// ---------------------------------------------------------------------------
// LN kernel: gates + bias -> cell = LN(f*c + i*g); writes cell (d_out 2nd
// half) and s = o*tanh(cell) pre-split to bf16 hi/lo for GEMM2.
// ---------------------------------------------------------------------------
__device__ __forceinline__ float sigmoidf_(float v) {
    return 1.0f / (1.0f + expf(-v));
}

__global__ __launch_bounds__(256) void ln_kernel(
    const float* __restrict__ cprev,
    const float* __restrict__ bias,
    const float* __restrict__ gamma,
    const float* __restrict__ beta,
    float* __restrict__ out_cell)
{
    const int b = blockIdx.x;
    const int tid = threadIdx.x;
    __shared__ float red[16];

    const size_t gbase = (size_t)b * 2048;
    const size_t hbase = (size_t)b * HDIM;

    float cr[2], og[2];
    #pragma unroll
    for (int e = 0; e < 2; e++) {
        int h = tid + e * 256;
        float ig = sigmoidf_(g_gates[gbase + 0 * 512 + h] + bias[0 * 512 + h]);
        float fg = sigmoidf_(g_gates[gbase + 1 * 512 + h] + bias[1 * 512 + h]);
        float gg = tanhf    (g_gates[gbase + 2 * 512 + h] + bias[2 * 512 + h]);
        og[e]    = sigmoidf_(g_gates[gbase + 3 * 512 + h] + bias[3 * 512 + h]);
        cr[e] = fg * cprev[hbase + h] + ig * gg;
    }

    float s = cr[0] + cr[1];
    #pragma unroll
    for (int o = 16; o > 0; o >>= 1) s += __shfl_down_sync(0xffffffffu, s, o);
    if ((tid & 31) == 0) red[tid >> 5] = s;
    __syncthreads();
    if (tid < 32) {
        float t = (tid < 8) ? red[tid] : 0.f;
        #pragma unroll
        for (int o = 4; o > 0; o >>= 1) t += __shfl_down_sync(0xffffffffu, t, o);
        if (tid == 0) red[0] = t;
    }
    __syncthreads();
    const float mu = red[0] * (1.0f / HDIM);
    __syncthreads();

    float d0 = cr[0] - mu, d1 = cr[1] - mu;
    float sv = d0 * d0 + d1 * d1;
    #pragma unroll
    for (int o = 16; o > 0; o >>= 1) sv += __shfl_down_sync(0xffffffffu, sv, o);
    if ((tid & 31) == 0) red[tid >> 5] = sv;
    __syncthreads();
    if (tid < 32) {
        float t = (tid < 8) ? red[tid] : 0.f;
        #pragma unroll
        for (int o = 4; o > 0; o >>= 1) t += __shfl_down_sync(0xffffffffu, t, o);
        if (tid == 0) red[0] = t;
    }
    __syncthreads();
    const float rstd = rsqrtf(red[0] * (1.0f / HDIM) + LN_EPS);

    #pragma unroll
    for (int e = 0; e < 2; e++) {
        int h = tid + e * 256;
        float d = (e == 0) ? d0 : d1;
        float cell = d * rstd * gamma[h] + beta[h];
        out_cell[hbase + h] = cell;
        float sval = og[e] * tanhf(cell);
        uint16_t hb, lb;
        bf16split(sval, hb, lb);
        *(uint16_t*)&g_shi[hbase + h] = hb;
        *(uint16_t*)&g_slo[hbase + h] = lb;
    }
}

// ---------------------------------------------------------------------------
extern "C" void kernel_launch(void* const* d_in, const int* in_sizes, int n_in,
                              void* d_out, int out_size)
{
    const float* x     = (const float*)d_in[0];
    const float* hprev = (const float*)d_in[1];
    const float* cprev = (const float*)d_in[2];
    const float* W     = (const float*)d_in[3];
    const float* bias  = (const float*)d_in[4];
    const float* gamma = (const float*)d_in[5];
    const float* beta  = (const float*)d_in[6];
    const float* Wp    = (const float*)d_in[7];

    float* out      = (float*)d_out;
    float* out_cell = (float*)d_out + (size_t)BSZ * HDIM;

    float* gates_ptr;
    cudaGetSymbolAddress((void**)&gates_ptr, g_gates);
    __nv_bfloat16 *chi, *clo, *whi, *wlo, *wphi, *wplo, *shi, *slo;
    cudaGetSymbolAddress((void**)&chi,  g_chi);
    cudaGetSymbolAddress((void**)&clo,  g_clo);
    cudaGetSymbolAddress((void**)&whi,  g_whi);
    cudaGetSymbolAddress((void**)&wlo,  g_wlo);
    cudaGetSymbolAddress((void**)&wphi, g_wphi);
    cudaGetSymbolAddress((void**)&wplo, g_wplo);
    cudaGetSymbolAddress((void**)&shi,  g_shi);
    cudaGetSymbolAddress((void**)&slo,  g_slo);

    cudaFuncSetAttribute(mma_gemm<32>, cudaFuncAttributeMaxDynamicSharedMemorySize, SMEM_BYTES);
    cudaFuncSetAttribute(mma_gemm<16>, cudaFuncAttributeMaxDynamicSharedMemorySize, SMEM_BYTES);

    // Pre-pass conversions
    conv_combined_kernel<<<BSZ, 256>>>(x, hprev);
    conv_mat_kernel<<<(2048 * 1024 / 4 + 255) / 256, 256>>>(W,  whi,  wlo,  2048 * 1024 / 4);
    conv_mat_kernel<<<(512 * 512 / 4 + 255) / 256, 256>>>(Wp, wphi, wplo, 512 * 512 / 4);

    // GEMM1: gates[B, 2048] = combined @ W^T  (K = 1024)
    dim3 g1(2048 / BN, BSZ / BM);   // 16 x 128
    mma_gemm<32><<<g1, 256, SMEM_BYTES>>>(chi, clo, whi, wlo, gates_ptr, 1024, 2048);

    // LN + elementwise (+ bf16 split of s)
    ln_kernel<<<BSZ, 256>>>(cprev, bias, gamma, beta, out_cell);

    // GEMM2: out[B, 512] = s @ Wp^T  (K = 512)
    dim3 g2(512 / BN, BSZ / BM);    // 4 x 128
    mma_gemm<16><<<g2, 256, SMEM_BYTES>>>(shi, slo, wphi, wplo, out, 512, 512);
}